// round 16
// baseline (speedup 1.0000x reference)
#include <cuda_runtime.h>
#include <math.h>

// x [L=4096, B=4, D=1024] fp32, channel-contiguous (BD = 4096 per timestep)
#define L      4096
#define B      4
#define D      1024
#define BD     (B * D)        // 4096 channels
#define C      128            // time chunks
#define LC     (L / C)        // 32 steps per chunk (x tile fits in registers)
#define NCB    16             // channel-blocks (256 ch each)
#define JOBS   (C * NCB)      // 2048 jobs == 2048 CTAs (ticket-ordered)
#define DEPTH  16             // |(c^32)^16| <= ~6e-9 for the slowest channel

// Spine: per-(chunk,channel) aggregates of zero-init local scans (4 MB, L2)
__device__ float g_er[C * BD], g_ei[C * BD];
// Publish flags laid out [cb][chunk] so a job's 16 predecessors are contiguous
__device__ int g_flag[NCB * C];
__device__ unsigned g_ticket, g_done;

__device__ __forceinline__ int ld_acquire(const int* p) {
    int v;
    asm volatile("ld.global.acquire.gpu.b32 %0, [%1];" : "=r"(v) : "l"(p));
    return v;
}
__device__ __forceinline__ void st_release(int* p, int v) {
    asm volatile("st.global.release.gpu.b32 [%0], %1;" :: "l"(p), "r"(v));
}

// ---------------------------------------------------------------------------
// One job per CTA: load 32-step x tile into registers (max MLP) -> zero-init
// scan -> publish aggregate -> parallel-spin lookback over 16 predecessors
// -> prefix -> replay from registers -> streaming stores.
// Fine job granularity + ticket order staggers CTAs so phase-1 DRAM reads of
// later chunks overlap phase-2 DRAM writes of earlier ones (mixed HBM stream).
// ---------------------------------------------------------------------------
__global__ void __launch_bounds__(256, 3)
spiral_scan(const float* __restrict__ x,
            const float* __restrict__ lmlg,
            const float* __restrict__ theta,
            const float* __restrict__ lci,
            float* __restrict__ out) {
    __shared__ unsigned s_ticket;
    if (threadIdx.x == 0) s_ticket = atomicAdd(&g_ticket, 1u);
    __syncthreads();
    int job   = (int)s_ticket;
    int chunk = job >> 4;                    // chunk-major: preds get lower tickets
    int cb    = job & (NCB - 1);
    int bd    = (cb << 8) | threadIdx.x;
    int d     = bd & (D - 1);

    // ---- coefficients (fp32; error ~1e-6 vs 1e-3 budget) ----
    float gamma = __expf(-__expf(lmlg[d]));
    float snt, cst;
    __sincosf(theta[d], &snt, &cst);
    float cr = gamma * cst, ci = gamma * snt;
    float Ar = cr, Ai = ci;                  // A = c^32, 5 squarings
#pragma unroll
    for (int i = 0; i < 5; i++) {
        float t = Ar * Ar - Ai * Ai;
        Ai = 2.f * Ar * Ai;
        Ar = t;
    }

    // ---- load the whole tile into registers: 32 independent loads ----
    float xv[LC];
    const float* xp = x + (size_t)chunk * LC * BD + bd;
#pragma unroll
    for (int k = 0; k < LC; k++)
        xv[k] = __ldg(xp + (size_t)k * BD);

    // ---- zero-init local scan -> aggregate E ----
    float sr = 0.f, si = 0.f;
#pragma unroll
    for (int k = 0; k < LC; k++) {
        float nr = fmaf(cr, sr, fmaf(-ci, si, xv[k]));
        float ni = fmaf(ci, sr, cr * si);
        sr = nr; si = ni;
    }
    size_t sidx = (size_t)chunk * BD + bd;
    g_er[sidx] = sr;
    g_ei[sidx] = si;

    // ---- publish flag, then parallel spin: thread k waits on pred chunk-1-k ----
    __threadfence();
    __syncthreads();
    int kmax = (chunk < DEPTH) ? chunk : DEPTH;
    if (threadIdx.x == 0) st_release(&g_flag[cb * C + chunk], 1);
    if ((int)threadIdx.x < kmax) {
        const int* fp = &g_flag[cb * C + (chunk - 1 - (int)threadIdx.x)];
        while (ld_acquire(fp) == 0) __nanosleep(32);
    }
    __syncthreads();                         // all preds published

    // ---- prefix: P = sum_{k=1..kmax} A^{k-1} E_{chunk-k} (+ A^chunk seed) ----
    float accR = 0.f, accI = 0.f;
    float pwR = 1.f, pwI = 0.f;              // A^(k-1)
#pragma unroll
    for (int k = 1; k <= DEPTH; k++) {
        if (k > kmax) break;
        size_t j = (size_t)(chunk - k) * BD + bd;
        float eR = g_er[j];
        float eI = g_ei[j];
        accR = fmaf(pwR, eR, fmaf(-pwI, eI, accR));
        accI = fmaf(pwR, eI, fmaf(pwI, eR, accI));
        float t = pwR * Ar - pwI * Ai;
        pwI = fmaf(pwR, Ai, pwI * Ar);
        pwR = t;
    }
    float pr, pi;
    if (chunk == kmax) {                     // window reached t=0: exact seed
        float seed = lci[d];
        pr = fmaf(pwR, seed, accR);
        pi = fmaf(pwI, seed, accI);
    } else {                                 // truncated history (~6e-9)
        pr = accR;
        pi = accI;
    }

    // ---- replay from registers; out = Re(s)*x, streaming stores ----
    sr = pr; si = pi;
    float* op = out + (size_t)chunk * LC * BD + bd;
#pragma unroll
    for (int k = 0; k < LC; k++) {
        float nr = fmaf(cr, sr, fmaf(-ci, si, xv[k]));
        float ni = fmaf(ci, sr, cr * si);
        sr = nr; si = ni;
        __stcs(op + (size_t)k * BD, nr * xv[k]);
    }

    // ---- self-reset for graph replay: last CTA zeroes all control state ----
    __shared__ int s_last;
    __syncthreads();
    if (threadIdx.x == 0) {
        unsigned n = atomicAdd(&g_done, 1u);
        s_last = (n == (unsigned)(gridDim.x - 1)) ? 1 : 0;
    }
    __syncthreads();
    if (s_last) {
        for (int i = threadIdx.x; i < NCB * C; i += 256) g_flag[i] = 0;
        if (threadIdx.x == 0) { g_done = 0u; g_ticket = 0u; }
        __threadfence();
    }
}

// ---------------------------------------------------------------------------
extern "C" void kernel_launch(void* const* d_in, const int* in_sizes, int n_in,
                              void* d_out, int out_size) {
    const float* x    = (const float*)d_in[0];  // [L,B,D]
    const float* lmlg = (const float*)d_in[1];  // [D]
    const float* th   = (const float*)d_in[2];  // [D]
    const float* lci  = (const float*)d_in[3];  // [D]
    float* out = (float*)d_out;

    spiral_scan<<<JOBS, 256>>>(x, lmlg, th, lci, out);
}